// round 1
// baseline (speedup 1.0000x reference)
#include <cuda_runtime.h>
#include <cstddef>

#define Bz   4
#define Nn   2048
#define Dd   64
#define Hh   8
#define VD   124
#define OUTF 992
#define BN   (Bz * Nn)          // 8192
#define INNER 512
#define ATTN_OFF ((size_t)BN * Dd)   // 524288 floats

// ---------------- scratch (allocation-free: __device__ globals) -------------
__device__ float g_q[(size_t)Bz * Hh * Nn * Dd];     // (b,h,n,dh)   16 MB
__device__ float g_k[(size_t)Bz * Hh * Nn * Dd];     // (b,h,n,dh)   16 MB
__device__ float g_v[(size_t)BN * VD];               // (b,n,124)     4 MB
__device__ float g_o992[(size_t)BN * OUTF];          // (b,n,992)    31 MB

// ---------------------------------------------------------------------------
// Kernel 1: qk = x @ W_qk^T, scattered into q/k with (b,h,n,dh) layout.
// M=8192, Ncol=1024, K=64. 64x64 tiles, 4x4 microtile, K-chunks of 16.
// ---------------------------------------------------------------------------
__global__ __launch_bounds__(256) void qk_proj_kernel(
    const float* __restrict__ x, const float* __restrict__ Wqk)
{
    __shared__ float As[16][68];   // [kk][row]
    __shared__ float Bs[16][68];   // [kk][col]
    const int tid = threadIdx.x;
    const int tx = tid & 15, ty = tid >> 4;
    const int row0 = blockIdx.x * 64;
    const int col0 = blockIdx.y * 64;

    float acc[4][4] = {};
    for (int k0 = 0; k0 < 64; k0 += 16) {
        const int r  = tid >> 2;          // 0..63
        const int kq = (tid & 3) << 2;    // 0,4,8,12
        float4 a = *(const float4*)&x[(size_t)(row0 + r) * Dd + k0 + kq];
        As[kq + 0][r] = a.x; As[kq + 1][r] = a.y;
        As[kq + 2][r] = a.z; As[kq + 3][r] = a.w;
        float4 b = *(const float4*)&Wqk[(size_t)(col0 + r) * Dd + k0 + kq];
        Bs[kq + 0][r] = b.x; Bs[kq + 1][r] = b.y;
        Bs[kq + 2][r] = b.z; Bs[kq + 3][r] = b.w;
        __syncthreads();
        #pragma unroll
        for (int kk = 0; kk < 16; kk++) {
            float av[4], bv[4];
            *(float4*)av = *(const float4*)&As[kk][ty * 4];
            *(float4*)bv = *(const float4*)&Bs[kk][tx * 4];
            #pragma unroll
            for (int m = 0; m < 4; m++)
                #pragma unroll
                for (int n = 0; n < 4; n++)
                    acc[m][n] = fmaf(av[m], bv[n], acc[m][n]);
        }
        __syncthreads();
    }

    const bool is_q = (col0 < INNER);
    const int  cb   = is_q ? col0 : (col0 - INNER);
    const int  h    = cb / 64;
    float* dst = is_q ? g_q : g_k;
    #pragma unroll
    for (int m = 0; m < 4; m++) {
        const int r  = row0 + ty * 4 + m;
        const int b  = r / Nn;
        const int nn = r % Nn;
        float* p = dst + (((size_t)(b * Hh + h) * Nn + nn) * Dd + tx * 4);
        float4 v = make_float4(acc[m][0], acc[m][1], acc[m][2], acc[m][3]);
        *(float4*)p = v;
    }
}

// ---------------------------------------------------------------------------
// Kernel 2: conv value. One warp per (b,n) row. x row (64) -> h1 (2x40) -> v (124)
// ---------------------------------------------------------------------------
__global__ __launch_bounds__(256) void conv_kernel(
    const float* __restrict__ x,
    const float* __restrict__ w1, const float* __restrict__ b1,
    const float* __restrict__ w2, const float* __restrict__ b2)
{
    __shared__ float sx[8][64];
    __shared__ float sh1[8][80];
    const int w    = threadIdx.x >> 5;
    const int lane = threadIdx.x & 31;
    const int row  = blockIdx.x * 8 + w;

    sx[w][lane]      = x[(size_t)row * Dd + lane];
    sx[w][lane + 32] = x[(size_t)row * Dd + 32 + lane];
    __syncwarp();

    for (int idx = lane; idx < 80; idx += 32) {
        const int c = idx / 40, p = idx % 40;
        float s = b1[c];
        #pragma unroll
        for (int t = 0; t < 25; t++)
            s = fmaf(sx[w][p + t], w1[c * 25 + t], s);
        sh1[w][idx] = s;
    }
    __syncwarp();

    for (int idx = lane; idx < VD; idx += 32) {
        const int c2 = idx / 31, p = idx % 31;
        float s = b2[c2];
        #pragma unroll
        for (int c1 = 0; c1 < 2; c1++)
            #pragma unroll
            for (int t = 0; t < 10; t++)
                s = fmaf(sh1[w][c1 * 40 + p + t], w2[(c2 * 2 + c1) * 10 + t], s);
        g_v[(size_t)row * VD + idx] = s;
    }
}

// ---------------------------------------------------------------------------
// Kernel 3: dots = scale * Q K^T per (b,h). M=N=2048, K=64.
// 128x128 tile, 8x8 microtile, K-chunks of 16. Output -> attn buffer (unnormalized)
// ---------------------------------------------------------------------------
__global__ __launch_bounds__(256) void dots_kernel(float* __restrict__ attn)
{
    __shared__ float As[16][132];  // [kk][row]
    __shared__ float Bs[16][132];  // [kk][col]
    const int bh = blockIdx.z;
    const float* Q = g_q + (size_t)bh * Nn * Dd;
    const float* K = g_k + (size_t)bh * Nn * Dd;
    float* Cb = attn + (size_t)bh * Nn * Nn;
    const int i0 = blockIdx.y * 128;
    const int j0 = blockIdx.x * 128;
    const int tid = threadIdx.x;
    const int tx = tid & 15, ty = tid >> 4;

    float acc[8][8] = {};
    for (int k0 = 0; k0 < 64; k0 += 16) {
        #pragma unroll
        for (int l = 0; l < 2; l++) {
            const int f  = tid * 2 + l;       // 0..511
            const int r  = f >> 2;            // 0..127
            const int kq = (f & 3) << 2;
            float4 a = *(const float4*)&Q[(size_t)(i0 + r) * Dd + k0 + kq];
            As[kq + 0][r] = a.x; As[kq + 1][r] = a.y;
            As[kq + 2][r] = a.z; As[kq + 3][r] = a.w;
            float4 b = *(const float4*)&K[(size_t)(j0 + r) * Dd + k0 + kq];
            Bs[kq + 0][r] = b.x; Bs[kq + 1][r] = b.y;
            Bs[kq + 2][r] = b.z; Bs[kq + 3][r] = b.w;
        }
        __syncthreads();
        #pragma unroll
        for (int kk = 0; kk < 16; kk++) {
            float av[8], bv[8];
            *(float4*)&av[0] = *(const float4*)&As[kk][ty * 8];
            *(float4*)&av[4] = *(const float4*)&As[kk][ty * 8 + 4];
            *(float4*)&bv[0] = *(const float4*)&Bs[kk][tx * 8];
            *(float4*)&bv[4] = *(const float4*)&Bs[kk][tx * 8 + 4];
            #pragma unroll
            for (int m = 0; m < 8; m++)
                #pragma unroll
                for (int n = 0; n < 8; n++)
                    acc[m][n] = fmaf(av[m], bv[n], acc[m][n]);
        }
        __syncthreads();
    }

    const float scale = 0.125f;   // 64^-0.5
    #pragma unroll
    for (int m = 0; m < 8; m++) {
        float* cr = Cb + (size_t)(i0 + ty * 8 + m) * Nn + j0 + tx * 8;
        float4 v0 = make_float4(acc[m][0] * scale, acc[m][1] * scale,
                                acc[m][2] * scale, acc[m][3] * scale);
        float4 v1 = make_float4(acc[m][4] * scale, acc[m][5] * scale,
                                acc[m][6] * scale, acc[m][7] * scale);
        *(float4*)cr       = v0;
        *(float4*)(cr + 4) = v1;
    }
}

// ---------------------------------------------------------------------------
// Kernel 4: row softmax in place over attn (65536 rows x 2048)
// ---------------------------------------------------------------------------
__global__ __launch_bounds__(256) void softmax_kernel(float* __restrict__ attn)
{
    __shared__ float red[8];
    const size_t row = blockIdx.x;
    float4* p = (float4*)(attn + row * (size_t)Nn);
    const int tid  = threadIdx.x;
    const int lane = tid & 31, wid = tid >> 5;

    float4 v0 = p[tid];
    float4 v1 = p[tid + 256];

    float m = fmaxf(fmaxf(fmaxf(v0.x, v0.y), fmaxf(v0.z, v0.w)),
                    fmaxf(fmaxf(v1.x, v1.y), fmaxf(v1.z, v1.w)));
    #pragma unroll
    for (int o = 16; o; o >>= 1) m = fmaxf(m, __shfl_xor_sync(0xffffffffu, m, o));
    if (lane == 0) red[wid] = m;
    __syncthreads();
    m = red[0];
    #pragma unroll
    for (int i = 1; i < 8; i++) m = fmaxf(m, red[i]);
    __syncthreads();

    v0.x = expf(v0.x - m); v0.y = expf(v0.y - m);
    v0.z = expf(v0.z - m); v0.w = expf(v0.w - m);
    v1.x = expf(v1.x - m); v1.y = expf(v1.y - m);
    v1.z = expf(v1.z - m); v1.w = expf(v1.w - m);

    float s = v0.x + v0.y + v0.z + v0.w + v1.x + v1.y + v1.z + v1.w;
    #pragma unroll
    for (int o = 16; o; o >>= 1) s += __shfl_xor_sync(0xffffffffu, s, o);
    if (lane == 0) red[wid] = s;
    __syncthreads();
    s = red[0] + red[1] + red[2] + red[3] + red[4] + red[5] + red[6] + red[7];
    const float inv = 1.0f / s;

    v0.x *= inv; v0.y *= inv; v0.z *= inv; v0.w *= inv;
    v1.x *= inv; v1.y *= inv; v1.z *= inv; v1.w *= inv;
    p[tid]       = v0;
    p[tid + 256] = v1;
}

// ---------------------------------------------------------------------------
// Kernel 5: out992[b, i, h*124 + c] = sum_j attn[b,h,i,j] * v[b,j,c]
// M=2048, Ncol=124 (padded 128), K=2048. 128x128 tile, 8x8 microtile, K-chunks 16.
// ---------------------------------------------------------------------------
__global__ __launch_bounds__(256) void av_kernel(const float* __restrict__ attn)
{
    __shared__ float As[16][132];  // [kk][row]
    __shared__ float Vs[16][132];  // [kk][col]
    const int bh = blockIdx.z;
    const int b  = bh / Hh, h = bh % Hh;
    const float* A = attn + (size_t)bh * Nn * Nn;
    const float* V = g_v  + (size_t)b * Nn * VD;
    const int i0 = blockIdx.x * 128;
    const int tid = threadIdx.x;
    const int tx = tid & 15, ty = tid >> 4;

    float acc[8][8] = {};
    for (int k0 = 0; k0 < Nn; k0 += 16) {
        #pragma unroll
        for (int l = 0; l < 2; l++) {
            const int f  = tid * 2 + l;
            const int r  = f >> 2;
            const int kq = (f & 3) << 2;
            float4 a = *(const float4*)&A[(size_t)(i0 + r) * Nn + k0 + kq];
            As[kq + 0][r] = a.x; As[kq + 1][r] = a.y;
            As[kq + 2][r] = a.z; As[kq + 3][r] = a.w;
        }
        #pragma unroll
        for (int l = 0; l < 8; l++) {
            const int idx = tid + l * 256;       // 0..2047
            const int kk = idx >> 7, n = idx & 127;
            Vs[kk][n] = (n < VD) ? V[(size_t)(k0 + kk) * VD + n] : 0.0f;
        }
        __syncthreads();
        #pragma unroll
        for (int kk = 0; kk < 16; kk++) {
            float av[8], bv[8];
            *(float4*)&av[0] = *(const float4*)&As[kk][ty * 8];
            *(float4*)&av[4] = *(const float4*)&As[kk][ty * 8 + 4];
            *(float4*)&bv[0] = *(const float4*)&Vs[kk][tx * 8];
            *(float4*)&bv[4] = *(const float4*)&Vs[kk][tx * 8 + 4];
            #pragma unroll
            for (int m = 0; m < 8; m++)
                #pragma unroll
                for (int n = 0; n < 8; n++)
                    acc[m][n] = fmaf(av[m], bv[n], acc[m][n]);
        }
        __syncthreads();
    }

    float* O = g_o992 + (size_t)b * Nn * OUTF + (size_t)h * VD;
    #pragma unroll
    for (int m = 0; m < 8; m++) {
        const int i = i0 + ty * 8 + m;
        #pragma unroll
        for (int n = 0; n < 8; n++) {
            const int c = tx * 8 + n;
            if (c < VD) O[(size_t)i * OUTF + c] = acc[m][n];
        }
    }
}

// ---------------------------------------------------------------------------
// Kernel 6: out = out992 @ W_out^T + b_out. M=8192, Ncol=64, K=992.
// 64x64 tile, 4x4 microtile, K-chunks of 16.
// ---------------------------------------------------------------------------
__global__ __launch_bounds__(256) void outproj_kernel(
    const float* __restrict__ Wout, const float* __restrict__ bout,
    float* __restrict__ out)
{
    __shared__ float As[16][68];
    __shared__ float Bs[16][68];
    const int i0 = blockIdx.x * 64;
    const int tid = threadIdx.x;
    const int tx = tid & 15, ty = tid >> 4;

    float acc[4][4] = {};
    for (int k0 = 0; k0 < OUTF; k0 += 16) {
        const int r  = tid >> 2;
        const int kq = (tid & 3) << 2;
        float4 a = *(const float4*)&g_o992[(size_t)(i0 + r) * OUTF + k0 + kq];
        As[kq + 0][r] = a.x; As[kq + 1][r] = a.y;
        As[kq + 2][r] = a.z; As[kq + 3][r] = a.w;
        float4 w = *(const float4*)&Wout[(size_t)r * OUTF + k0 + kq];
        Bs[kq + 0][r] = w.x; Bs[kq + 1][r] = w.y;
        Bs[kq + 2][r] = w.z; Bs[kq + 3][r] = w.w;
        __syncthreads();
        #pragma unroll
        for (int kk = 0; kk < 16; kk++) {
            float av[4], bv[4];
            *(float4*)av = *(const float4*)&As[kk][ty * 4];
            *(float4*)bv = *(const float4*)&Bs[kk][tx * 4];
            #pragma unroll
            for (int m = 0; m < 4; m++)
                #pragma unroll
                for (int n = 0; n < 4; n++)
                    acc[m][n] = fmaf(av[m], bv[n], acc[m][n]);
        }
        __syncthreads();
    }

    #pragma unroll
    for (int m = 0; m < 4; m++) {
        const int r = i0 + ty * 4 + m;
        float4 v = make_float4(acc[m][0] + bout[tx * 4 + 0],
                               acc[m][1] + bout[tx * 4 + 1],
                               acc[m][2] + bout[tx * 4 + 2],
                               acc[m][3] + bout[tx * 4 + 3]);
        *(float4*)&out[(size_t)r * Dd + tx * 4] = v;
    }
}

// ---------------------------------------------------------------------------
extern "C" void kernel_launch(void* const* d_in, const int* in_sizes, int n_in,
                              void* d_out, int out_size)
{
    const float* x    = (const float*)d_in[0];
    const float* Wqk  = (const float*)d_in[1];
    const float* w1   = (const float*)d_in[2];
    const float* b1   = (const float*)d_in[3];
    const float* w2   = (const float*)d_in[4];
    const float* b2   = (const float*)d_in[5];
    const float* Wout = (const float*)d_in[6];
    const float* bout = (const float*)d_in[7];

    float* out  = (float*)d_out;
    float* attn = out + ATTN_OFF;

    qk_proj_kernel<<<dim3(BN / 64, 1024 / 64), 256>>>(x, Wqk);
    conv_kernel<<<BN / 8, 256>>>(x, w1, b1, w2, b2);
    dots_kernel<<<dim3(Nn / 128, Nn / 128, Bz * Hh), 256>>>(attn);
    softmax_kernel<<<Bz * Hh * Nn, 256>>>(attn);
    av_kernel<<<dim3(Nn / 128, 1, Bz * Hh), 256>>>(attn);
    outproj_kernel<<<BN / 64, 256>>>(Wout, bout, out);
}

// round 4
// speedup vs baseline: 1.7189x; 1.7189x over previous
#include <cuda_runtime.h>
#include <cuda_bf16.h>
#include <cstdint>
#include <cstddef>

#define Bz   4
#define Nn   2048
#define Dd   64
#define Hh   8
#define VD   124
#define OUTF 992
#define BN   (Bz * Nn)          // 8192
#define INNER 512
#define ATTN_OFF ((size_t)BN * Dd)   // 524288 floats

// ======================= PTX helpers (portable, sm_80+) =====================
__device__ __forceinline__ uint32_t smem_to_u32(const void* smem_ptr) {
    uint32_t addr;
    asm("{ .reg .u64 tmp; cvta.to.shared.u64 tmp, %1; cvt.u32.u64 %0, tmp; }"
        : "=r"(addr) : "l"(smem_ptr));
    return addr;
}

__device__ __forceinline__ void ldsm4(uint32_t* r, uint32_t addr) {
    asm volatile("ldmatrix.sync.aligned.m8n8.x4.shared.b16 {%0,%1,%2,%3}, [%4];"
        : "=r"(r[0]), "=r"(r[1]), "=r"(r[2]), "=r"(r[3]) : "r"(addr));
}

__device__ __forceinline__ void mma16816(float* d, const uint32_t* a,
                                         uint32_t b0, uint32_t b1) {
    asm volatile(
        "mma.sync.aligned.m16n8k16.row.col.f32.bf16.bf16.f32 "
        "{%0,%1,%2,%3}, {%4,%5,%6,%7}, {%8,%9}, {%0,%1,%2,%3};"
        : "+f"(d[0]), "+f"(d[1]), "+f"(d[2]), "+f"(d[3])
        : "r"(a[0]), "r"(a[1]), "r"(a[2]), "r"(a[3]), "r"(b0), "r"(b1));
}

#define CP_ASYNC16(daddr, sptr) \
    asm volatile("cp.async.cg.shared.global [%0], [%1], 16;" \
        :: "r"(daddr), "l"(sptr) : "memory")
#define CP_ASYNC_WAIT_ALL() asm volatile("cp.async.wait_all;" ::: "memory")

// bf16 split (hi + lo)
__device__ __forceinline__ void bf16_split(float v, unsigned short& hs, unsigned short& ls) {
    __nv_bfloat16 bh = __float2bfloat16(v);
    float res = v - __bfloat162float(bh);
    __nv_bfloat16 bl = __float2bfloat16(res);
    hs = __bfloat16_as_ushort(bh);
    ls = __bfloat16_as_ushort(bl);
}

// ======================= scratch (__device__ globals) =======================
__device__ float    g_v[(size_t)BN * VD];                 // (b,n,124) fp32
__device__ float    g_o992[(size_t)BN * OUTF];            // (b,n,992) fp32
// Q/K bf16 hi/lo, plain layout [bh][n][64 halves] = 32 u32/row
__device__ uint32_t g_qh[(size_t)Bz * Hh * Nn * 32];
__device__ uint32_t g_ql[(size_t)Bz * Hh * Nn * 32];
__device__ uint32_t g_kh[(size_t)Bz * Hh * Nn * 32];
__device__ uint32_t g_kl[(size_t)Bz * Hh * Nn * 32];
// V^T bf16 hi/lo chunk tiles: [b][kc(32)][n=128][kk=64 halves] plain
__device__ uint32_t g_vth[(size_t)Bz * 32 * 4096];
__device__ uint32_t g_vtl[(size_t)Bz * 32 * 4096];

// Shared GEMM core: 3-pass split-bf16, warp tile 32x64, K-chunk 64.
// Rows padded to 72 halves (144 bytes).
__device__ __forceinline__ void mma_block(
    float acc[2][8][4], uint32_t sbase,
    uint32_t aoffH, uint32_t aoffL, uint32_t boffH, uint32_t boffL,
    int ar, int bc, int lane)
{
    const uint32_t arow  = (uint32_t)(lane & 15);
    const uint32_t acolb = (uint32_t)((lane >> 4) * 16);
    const uint32_t brow  = (uint32_t)((lane & 7) + ((lane >> 4) << 3));
    const uint32_t bcolb = (uint32_t)(((lane >> 3) & 1) * 16);
    #pragma unroll
    for (int pass = 0; pass < 3; pass++) {
        const uint32_t Ab = sbase + (pass == 1 ? aoffL : aoffH);
        const uint32_t Bb = sbase + (pass == 2 ? boffL : boffH);
        #pragma unroll
        for (int ks = 0; ks < 4; ks++) {
            uint32_t a[2][4], bb[4][4];
            #pragma unroll
            for (int t = 0; t < 2; t++)
                ldsm4(a[t], Ab + (uint32_t)(ar + t * 16 + arow) * 144u + ks * 32u + acolb);
            #pragma unroll
            for (int p = 0; p < 4; p++)
                ldsm4(bb[p], Bb + (uint32_t)(bc + p * 16 + brow) * 144u + ks * 32u + bcolb);
            #pragma unroll
            for (int t = 0; t < 2; t++)
                #pragma unroll
                for (int p = 0; p < 4; p++) {
                    mma16816(acc[t][2 * p],     a[t], bb[p][0], bb[p][1]);
                    mma16816(acc[t][2 * p + 1], a[t], bb[p][2], bb[p][3]);
                }
        }
    }
}

// ---------------------------------------------------------------------------
// Kernel 1: qk = x @ W_qk^T -> split-bf16 q/k (plain layout)
// ---------------------------------------------------------------------------
__global__ __launch_bounds__(256) void qk_proj_kernel(
    const float* __restrict__ x, const float* __restrict__ Wqk)
{
    __shared__ float As[16][68];
    __shared__ float Bs[16][68];
    const int tid = threadIdx.x;
    const int tx = tid & 15, ty = tid >> 4;
    const int row0 = blockIdx.x * 64;
    const int col0 = blockIdx.y * 64;

    float acc[4][4] = {};
    for (int k0 = 0; k0 < 64; k0 += 16) {
        const int r  = tid >> 2;
        const int kq = (tid & 3) << 2;
        float4 a = *(const float4*)&x[(size_t)(row0 + r) * Dd + k0 + kq];
        As[kq + 0][r] = a.x; As[kq + 1][r] = a.y;
        As[kq + 2][r] = a.z; As[kq + 3][r] = a.w;
        float4 b = *(const float4*)&Wqk[(size_t)(col0 + r) * Dd + k0 + kq];
        Bs[kq + 0][r] = b.x; Bs[kq + 1][r] = b.y;
        Bs[kq + 2][r] = b.z; Bs[kq + 3][r] = b.w;
        __syncthreads();
        #pragma unroll
        for (int kk = 0; kk < 16; kk++) {
            float av[4], bv[4];
            *(float4*)av = *(const float4*)&As[kk][ty * 4];
            *(float4*)bv = *(const float4*)&Bs[kk][tx * 4];
            #pragma unroll
            for (int m = 0; m < 4; m++)
                #pragma unroll
                for (int n = 0; n < 4; n++)
                    acc[m][n] = fmaf(av[m], bv[n], acc[m][n]);
        }
        __syncthreads();
    }

    const bool is_q = (col0 < INNER);
    const int  cb   = is_q ? col0 : (col0 - INNER);
    const int  h    = cb >> 6;
    uint32_t* dh = is_q ? g_qh : g_kh;
    uint32_t* dl = is_q ? g_ql : g_kl;
    #pragma unroll
    for (int m = 0; m < 4; m++) {
        const int r  = row0 + ty * 4 + m;
        const int b  = r / Nn;
        const int nn = r % Nn;
        const size_t base = ((size_t)(b * Hh + h) * Nn + nn) * 32 + tx * 2;
        unsigned short h0, l0, h1, l1, h2, l2, h3, l3;
        bf16_split(acc[m][0], h0, l0);
        bf16_split(acc[m][1], h1, l1);
        bf16_split(acc[m][2], h2, l2);
        bf16_split(acc[m][3], h3, l3);
        dh[base]     = (uint32_t)h0 | ((uint32_t)h1 << 16);
        dh[base + 1] = (uint32_t)h2 | ((uint32_t)h3 << 16);
        dl[base]     = (uint32_t)l0 | ((uint32_t)l1 << 16);
        dl[base + 1] = (uint32_t)l2 | ((uint32_t)l3 << 16);
    }
}

// ---------------------------------------------------------------------------
// Kernel 2: conv value (fp32 -> g_v)
// ---------------------------------------------------------------------------
__global__ __launch_bounds__(256) void conv_kernel(
    const float* __restrict__ x,
    const float* __restrict__ w1, const float* __restrict__ b1,
    const float* __restrict__ w2, const float* __restrict__ b2)
{
    __shared__ float sx[8][64];
    __shared__ float sh1[8][80];
    const int w    = threadIdx.x >> 5;
    const int lane = threadIdx.x & 31;
    const int row  = blockIdx.x * 8 + w;

    sx[w][lane]      = x[(size_t)row * Dd + lane];
    sx[w][lane + 32] = x[(size_t)row * Dd + 32 + lane];
    __syncwarp();

    for (int idx = lane; idx < 80; idx += 32) {
        const int c = idx / 40, p = idx % 40;
        float s = b1[c];
        #pragma unroll
        for (int t = 0; t < 25; t++)
            s = fmaf(sx[w][p + t], w1[c * 25 + t], s);
        sh1[w][idx] = s;
    }
    __syncwarp();

    for (int idx = lane; idx < VD; idx += 32) {
        const int c2 = idx / 31, p = idx % 31;
        float s = b2[c2];
        #pragma unroll
        for (int c1 = 0; c1 < 2; c1++)
            #pragma unroll
            for (int t = 0; t < 10; t++)
                s = fmaf(sh1[w][c1 * 40 + p + t], w2[(c2 * 2 + c1) * 10 + t], s);
        g_v[(size_t)row * VD + idx] = s;
    }
}

// ---------------------------------------------------------------------------
// Kernel 2b: V -> transposed split-bf16 chunk tiles (plain layout)
// grid = Bz*32 blocks (tile: n=c 0..127, kk=j 0..63)
// ---------------------------------------------------------------------------
__global__ __launch_bounds__(256) void vconv_kernel()
{
    const int blk = blockIdx.x;
    const int b = blk >> 5, jc = blk & 31;
    const int j0 = jc * 64;
    unsigned short* oh = (unsigned short*)g_vth;
    unsigned short* ol = (unsigned short*)g_vtl;
    for (int e = threadIdx.x; e < 8192; e += 256) {
        const int c = e >> 6, jj = e & 63;
        float v = (c < VD) ? g_v[((size_t)b * Nn + j0 + jj) * VD + c] : 0.0f;
        unsigned short hh, ll;
        bf16_split(v, hh, ll);
        const size_t o = ((size_t)blk * 128 + c) * 64 + jj;
        oh[o] = hh;
        ol[o] = ll;
    }
}

// ---------------------------------------------------------------------------
// Kernel 3: dots = scale * Q K^T via mma.sync (3-pass split bf16)
// grid (16,16,32), 256 threads. dyn smem = 4 x 18432 = 73728 B.
// ---------------------------------------------------------------------------
__global__ __launch_bounds__(256) void dots_mma_kernel(float* __restrict__ attn)
{
    extern __shared__ char sm[];
    const int tid = threadIdx.x, lane = tid & 31, wid = tid >> 5;
    const int bh = blockIdx.z;
    const int i0 = blockIdx.y * 128, j0 = blockIdx.x * 128;

    const uint4* qh = (const uint4*)(g_qh + ((size_t)bh * Nn + i0) * 32);
    const uint4* ql = (const uint4*)(g_ql + ((size_t)bh * Nn + i0) * 32);
    const uint4* kh = (const uint4*)(g_kh + ((size_t)bh * Nn + j0) * 32);
    const uint4* kl = (const uint4*)(g_kl + ((size_t)bh * Nn + j0) * 32);
    for (int i = tid; i < 1024; i += 256) {
        const int row = i >> 3, q = i & 7;
        const int off = row * 144 + q * 16;
        *(uint4*)(sm + off)         = qh[i];
        *(uint4*)(sm + 18432 + off) = ql[i];
        *(uint4*)(sm + 36864 + off) = kh[i];
        *(uint4*)(sm + 55296 + off) = kl[i];
    }
    __syncthreads();

    const uint32_t sbase = smem_to_u32(sm);
    const int ar = (wid >> 1) * 32, bc = (wid & 1) * 64;
    float acc[2][8][4] = {};
    mma_block(acc, sbase, 0, 18432, 36864, 55296, ar, bc, lane);

    float* C = attn + (size_t)bh * Nn * Nn;
    #pragma unroll
    for (int t = 0; t < 2; t++) {
        const int r0 = i0 + ar + t * 16 + (lane >> 2);
        #pragma unroll
        for (int nt = 0; nt < 8; nt++) {
            const int c0 = j0 + bc + nt * 8 + (lane & 3) * 2;
            float2 u = make_float2(acc[t][nt][0] * 0.125f, acc[t][nt][1] * 0.125f);
            float2 v = make_float2(acc[t][nt][2] * 0.125f, acc[t][nt][3] * 0.125f);
            *(float2*)&C[(size_t)r0 * Nn + c0]       = u;
            *(float2*)&C[(size_t)(r0 + 8) * Nn + c0] = v;
        }
    }
}

// ---------------------------------------------------------------------------
// Kernel 4: row softmax in place (unchanged)
// ---------------------------------------------------------------------------
__global__ __launch_bounds__(256) void softmax_kernel(float* __restrict__ attn)
{
    __shared__ float red[8];
    const size_t row = blockIdx.x;
    float4* p = (float4*)(attn + row * (size_t)Nn);
    const int tid  = threadIdx.x;
    const int lane = tid & 31, wid = tid >> 5;

    float4 v0 = p[tid];
    float4 v1 = p[tid + 256];

    float m = fmaxf(fmaxf(fmaxf(v0.x, v0.y), fmaxf(v0.z, v0.w)),
                    fmaxf(fmaxf(v1.x, v1.y), fmaxf(v1.z, v1.w)));
    #pragma unroll
    for (int o = 16; o; o >>= 1) m = fmaxf(m, __shfl_xor_sync(0xffffffffu, m, o));
    if (lane == 0) red[wid] = m;
    __syncthreads();
    m = red[0];
    #pragma unroll
    for (int i = 1; i < 8; i++) m = fmaxf(m, red[i]);
    __syncthreads();

    v0.x = expf(v0.x - m); v0.y = expf(v0.y - m);
    v0.z = expf(v0.z - m); v0.w = expf(v0.w - m);
    v1.x = expf(v1.x - m); v1.y = expf(v1.y - m);
    v1.z = expf(v1.z - m); v1.w = expf(v1.w - m);

    float s = v0.x + v0.y + v0.z + v0.w + v1.x + v1.y + v1.z + v1.w;
    #pragma unroll
    for (int o = 16; o; o >>= 1) s += __shfl_xor_sync(0xffffffffu, s, o);
    if (lane == 0) red[wid] = s;
    __syncthreads();
    s = red[0] + red[1] + red[2] + red[3] + red[4] + red[5] + red[6] + red[7];
    const float inv = 1.0f / s;

    v0.x *= inv; v0.y *= inv; v0.z *= inv; v0.w *= inv;
    v1.x *= inv; v1.y *= inv; v1.z *= inv; v1.w *= inv;
    p[tid]       = v0;
    p[tid + 256] = v1;
}

// ---------------------------------------------------------------------------
// Kernel 5: AV via mma.sync (3-pass split bf16), cp.async double-buffered.
// grid (16,1,32), 256 threads.
// Stage layout (106496 B each, 2 stages = 212992 dyn smem):
//   +0      Ah (18432)   +18432 Al    +36864 Bh    +55296 Bl    +73728 Af32 (32768)
// ---------------------------------------------------------------------------
__global__ __launch_bounds__(256) void av_mma_kernel(const float* __restrict__ attn)
{
    extern __shared__ char sm[];
    const int tid = threadIdx.x, lane = tid & 31, wid = tid >> 5;
    const int bh = blockIdx.z;
    const int b = bh >> 3, h = bh & 7;
    const int i0 = blockIdx.x * 128;
    const uint32_t sbase = smem_to_u32(sm);

    const float* A0 = attn + ((size_t)bh * Nn + i0) * Nn;
    const int ar = (wid >> 1) * 32, bc = (wid & 1) * 64;

    auto issue = [&](int ic, uint32_t stg) {
        const char* vh = (const char*)g_vth + (size_t)(b * 32 + ic) * 16384;
        const char* vl = (const char*)g_vtl + (size_t)(b * 32 + ic) * 16384;
        for (int i = tid; i < 1024; i += 256) {
            const int row = i >> 3, q = i & 7;
            const uint32_t off = (uint32_t)(row * 144 + q * 16);
            CP_ASYNC16(sbase + stg + 36864 + off, vh + i * 16);
            CP_ASYNC16(sbase + stg + 55296 + off, vl + i * 16);
        }
        const float* As = A0 + ic * 64;
        for (int i = tid; i < 2048; i += 256) {
            const int row = i >> 4, c4 = (i & 15) * 4;
            CP_ASYNC16(sbase + stg + 73728 + (uint32_t)i * 16,
                       &As[(size_t)row * Nn + c4]);
        }
    };
    auto convert = [&](uint32_t stg) {
        char* st = sm + stg;
        for (int i = tid; i < 2048; i += 256) {
            float4 v = *(float4*)(st + 73728 + i * 16);
            const int row = i >> 4, c4 = (i & 15) * 4;
            unsigned short h0, l0, h1, l1, h2, l2, h3, l3;
            bf16_split(v.x, h0, l0); bf16_split(v.y, h1, l1);
            bf16_split(v.z, h2, l2); bf16_split(v.w, h3, l3);
            const int off = row * 144 + c4 * 2;
            *(uint32_t*)(st + off)             = (uint32_t)h0 | ((uint32_t)h1 << 16);
            *(uint32_t*)(st + off + 4)         = (uint32_t)h2 | ((uint32_t)h3 << 16);
            *(uint32_t*)(st + 18432 + off)     = (uint32_t)l0 | ((uint32_t)l1 << 16);
            *(uint32_t*)(st + 18432 + off + 4) = (uint32_t)l2 | ((uint32_t)l3 << 16);
        }
    };

    issue(0, 0);
    CP_ASYNC_WAIT_ALL();
    convert(0);
    __syncthreads();

    float acc[2][8][4] = {};
    for (int ic = 0; ic < 32; ic++) {
        const uint32_t cur = (uint32_t)(ic & 1) * 106496u;
        const uint32_t nxt = (uint32_t)((ic + 1) & 1) * 106496u;
        if (ic < 31) issue(ic + 1, nxt);
        mma_block(acc, sbase, cur, cur + 18432, cur + 36864, cur + 55296,
                  ar, bc, lane);
        if (ic < 31) {
            CP_ASYNC_WAIT_ALL();
            convert(nxt);
        }
        __syncthreads();
    }

    float* O = g_o992 + (size_t)b * Nn * OUTF + (size_t)h * VD;
    #pragma unroll
    for (int t = 0; t < 2; t++) {
        const int r0 = i0 + ar + t * 16 + (lane >> 2);
        #pragma unroll
        for (int nt = 0; nt < 8; nt++) {
            const int c0 = bc + nt * 8 + (lane & 3) * 2;
            if (c0 < VD) {
                float2 u = make_float2(acc[t][nt][0], acc[t][nt][1]);
                float2 v = make_float2(acc[t][nt][2], acc[t][nt][3]);
                *(float2*)&O[(size_t)r0 * OUTF + c0]       = u;
                *(float2*)&O[(size_t)(r0 + 8) * OUTF + c0] = v;
            }
        }
    }
}

// ---------------------------------------------------------------------------
// Kernel 6: out = out992 @ W_out^T + b_out (unchanged)
// ---------------------------------------------------------------------------
__global__ __launch_bounds__(256) void outproj_kernel(
    const float* __restrict__ Wout, const float* __restrict__ bout,
    float* __restrict__ out)
{
    __shared__ float As[16][68];
    __shared__ float Bs[16][68];
    const int i0 = blockIdx.x * 64;
    const int tid = threadIdx.x;
    const int tx = tid & 15, ty = tid >> 4;

    float acc[4][4] = {};
    for (int k0 = 0; k0 < OUTF; k0 += 16) {
        const int r  = tid >> 2;
        const int kq = (tid & 3) << 2;
        float4 a = *(const float4*)&g_o992[(size_t)(i0 + r) * OUTF + k0 + kq];
        As[kq + 0][r] = a.x; As[kq + 1][r] = a.y;
        As[kq + 2][r] = a.z; As[kq + 3][r] = a.w;
        float4 w = *(const float4*)&Wout[(size_t)r * OUTF + k0 + kq];
        Bs[kq + 0][r] = w.x; Bs[kq + 1][r] = w.y;
        Bs[kq + 2][r] = w.z; Bs[kq + 3][r] = w.w;
        __syncthreads();
        #pragma unroll
        for (int kk = 0; kk < 16; kk++) {
            float av[4], bv[4];
            *(float4*)av = *(const float4*)&As[kk][ty * 4];
            *(float4*)bv = *(const float4*)&Bs[kk][tx * 4];
            #pragma unroll
            for (int m = 0; m < 4; m++)
                #pragma unroll
                for (int n = 0; n < 4; n++)
                    acc[m][n] = fmaf(av[m], bv[n], acc[m][n]);
        }
        __syncthreads();
    }

    #pragma unroll
    for (int m = 0; m < 4; m++) {
        const int r = i0 + ty * 4 + m;
        float4 v = make_float4(acc[m][0] + bout[tx * 4 + 0],
                               acc[m][1] + bout[tx * 4 + 1],
                               acc[m][2] + bout[tx * 4 + 2],
                               acc[m][3] + bout[tx * 4 + 3]);
        *(float4*)&out[(size_t)r * Dd + tx * 4] = v;
    }
}

// ---------------------------------------------------------------------------
extern "C" void kernel_launch(void* const* d_in, const int* in_sizes, int n_in,
                              void* d_out, int out_size)
{
    const float* x    = (const float*)d_in[0];
    const float* Wqk  = (const float*)d_in[1];
    const float* w1   = (const float*)d_in[2];
    const float* b1   = (const float*)d_in[3];
    const float* w2   = (const float*)d_in[4];
    const float* b2   = (const float*)d_in[5];
    const float* Wout = (const float*)d_in[6];
    const float* bout = (const float*)d_in[7];

    float* out  = (float*)d_out;
    float* attn = out + ATTN_OFF;

    cudaFuncSetAttribute(dots_mma_kernel,
                         cudaFuncAttributeMaxDynamicSharedMemorySize, 73728);
    cudaFuncSetAttribute(av_mma_kernel,
                         cudaFuncAttributeMaxDynamicSharedMemorySize, 212992);

    qk_proj_kernel<<<dim3(BN / 64, 1024 / 64), 256>>>(x, Wqk);
    conv_kernel<<<BN / 8, 256>>>(x, w1, b1, w2, b2);
    vconv_kernel<<<Bz * 32, 256>>>();
    dots_mma_kernel<<<dim3(Nn / 128, Nn / 128, Bz * Hh), 256, 73728>>>(attn);
    softmax_kernel<<<Bz * Hh * Nn, 256>>>(attn);
    av_mma_kernel<<<dim3(Nn / 128, 1, Bz * Hh), 256, 212992>>>(attn);
    outproj_kernel<<<BN / 64, 256>>>(Wout, bout, out);
}